// round 1
// baseline (speedup 1.0000x reference)
#include <cuda_runtime.h>
#include <cstdint>

#define B_ 8
#define N_ 16384
#define M_ 1024
#define C_ 64
#define NS_ 32
#define COUT_ 67
#define R2_ 0.04f

// Scratch: transposed features (B, N, C) = 32 MB, and ball-query indices = 1 MB.
__device__ float g_ft[(size_t)B_ * N_ * C_];
__device__ int   g_idx[(size_t)B_ * M_ * NS_];

// ---------------------------------------------------------------------------
// Kernel 1: transpose features (B, C, N) -> (B, N, C), tiled 32x32 via smem.
// ---------------------------------------------------------------------------
__global__ void transpose_kernel(const float* __restrict__ f) {
    __shared__ float tile[32][33];
    const int b  = blockIdx.z;
    const int n0 = blockIdx.x * 32;
    const int c0 = blockIdx.y * 32;
    const int tx = threadIdx.x, ty = threadIdx.y;  // (32, 8)

    const float* src = f + (size_t)b * C_ * N_;
    float*       dst = g_ft + (size_t)b * N_ * C_;

#pragma unroll
    for (int i = 0; i < 32; i += 8)
        tile[ty + i][tx] = src[(size_t)(c0 + ty + i) * N_ + (n0 + tx)];
    __syncthreads();
#pragma unroll
    for (int i = 0; i < 32; i += 8)
        dst[(size_t)(n0 + ty + i) * C_ + (c0 + tx)] = tile[tx][ty + i];
}

// ---------------------------------------------------------------------------
// Kernel 2: ball query. One warp per query point; ordered index compaction
// via ballot+popc; early exit once 32 neighbors found (indices ascend, which
// equals the reference's sort-then-truncate).
// ---------------------------------------------------------------------------
__global__ void ballquery_kernel(const float* __restrict__ xyz,
                                 const float* __restrict__ new_xyz) {
    __shared__ int sidx[8][NS_];
    const int w    = threadIdx.x >> 5;
    const int lane = threadIdx.x & 31;
    const int q    = blockIdx.x * 8 + w;      // global query id, 0..8191
    const int b    = q >> 10;
    const int m    = q & (M_ - 1);

    const float* xb = xyz + (size_t)b * N_ * 3;
    const float* qp = new_xyz + ((size_t)b * M_ + m) * 3;
    const float qx = qp[0], qy = qp[1], qz = qp[2];

    int total = 0;
    for (int n0 = 0; n0 < N_; n0 += 32) {
        const int n = n0 + lane;
        const float dx = xb[n * 3 + 0] - qx;
        const float dy = xb[n * 3 + 1] - qy;
        const float dz = xb[n * 3 + 2] - qz;
        const float d2 = dx * dx + dy * dy + dz * dz;
        const bool  hit = d2 < R2_;
        const unsigned mask = __ballot_sync(0xffffffffu, hit);
        if (mask) {
            const int pos = total + __popc(mask & ((1u << lane) - 1u));
            if (hit && pos < NS_) sidx[w][pos] = n;
            total += __popc(mask);
            if (total >= NS_) break;
        }
    }
    __syncwarp();

    int v;
    if (total == 0) {
        v = N_ - 1;  // reference yields idx=N+1 everywhere -> clamped gather
    } else {
        const int first = sidx[w][0];
        v = (lane < total) ? sidx[w][lane] : first;
    }
    g_idx[(size_t)q * NS_ + lane] = v;
}

// ---------------------------------------------------------------------------
// Kernel 3: grouping. One block per (b, m). Gather 64 contiguous channels per
// index from the transposed features (256B coalesced per sample), plus the
// xyz diff; stage in a 67x33 smem tile; write output fully coalesced.
// ---------------------------------------------------------------------------
__global__ void group_kernel(const float* __restrict__ xyz,
                             const float* __restrict__ new_xyz,
                             float* __restrict__ out) {
    __shared__ int   sidx[NS_];
    __shared__ float tile[COUT_][33];

    const int bm = blockIdx.x;
    const int b  = bm >> 10;
    const int m  = bm & (M_ - 1);
    const int t  = threadIdx.x;          // 256 threads
    const int w  = t >> 5;
    const int lane = t & 31;

    if (t < NS_) sidx[t] = g_idx[(size_t)bm * NS_ + t];
    __syncthreads();

    const float* ftb = g_ft + (size_t)b * N_ * C_;
    const float* qp  = new_xyz + ((size_t)b * M_ + m) * 3;

#pragma unroll
    for (int k = 0; k < 4; k++) {
        const int s = w + k * 8;         // 8 warps cover 32 samples
        const int n = sidx[s];
        const float* col = ftb + (size_t)n * C_;
        tile[3 + lane][s]      = col[lane];
        tile[3 + 32 + lane][s] = col[lane + 32];
        if (lane < 3)
            tile[lane][s] = xyz[((size_t)b * N_ + n) * 3 + lane] - qp[lane];
    }
    __syncthreads();

    float* ob = out + ((size_t)b * COUT_ * M_ + m) * NS_;
    for (int e = t; e < COUT_ * NS_; e += 256) {
        const int c = e >> 5;
        const int s = e & 31;
        ob[(size_t)c * M_ * NS_ + s] = tile[c][s];
    }
}

// ---------------------------------------------------------------------------
extern "C" void kernel_launch(void* const* d_in, const int* in_sizes, int n_in,
                              void* d_out, int out_size) {
    const float* xyz = nullptr;
    const float* new_xyz = nullptr;
    const float* feats = nullptr;
    for (int i = 0; i < n_in; i++) {
        if (in_sizes[i] == B_ * N_ * 3)      xyz     = (const float*)d_in[i];
        else if (in_sizes[i] == B_ * M_ * 3) new_xyz = (const float*)d_in[i];
        else if (in_sizes[i] == B_ * C_ * N_) feats  = (const float*)d_in[i];
    }
    float* out = (float*)d_out;

    dim3 tgrid(N_ / 32, C_ / 32, B_);
    transpose_kernel<<<tgrid, dim3(32, 8)>>>(feats);

    ballquery_kernel<<<(B_ * M_) / 8, 256>>>(xyz, new_xyz);

    group_kernel<<<B_ * M_, 256>>>(xyz, new_xyz, out);
}

// round 3
// speedup vs baseline: 2.3863x; 2.3863x over previous
#include <cuda_runtime.h>
#include <cstdint>

#define B_ 8
#define N_ 16384
#define M_ 1024
#define C_ 64
#define NS_ 32
#define COUT_ 67
#define R2_ 0.04f
#define TILE_PTS 1024

// Scratch: transposed features (B, N, C) = 32 MB, and ball-query indices = 1 MB.
__device__ float g_ft[(size_t)B_ * N_ * C_];
__device__ int   g_idx[(size_t)B_ * M_ * NS_];

// ---------------------------------------------------------------------------
// Kernel 1: transpose features (B, C, N) -> (B, N, C), tiled 32x32 via smem.
// ---------------------------------------------------------------------------
__global__ void transpose_kernel(const float* __restrict__ f) {
    __shared__ float tile[32][33];
    const int b  = blockIdx.z;
    const int n0 = blockIdx.x * 32;
    const int c0 = blockIdx.y * 32;
    const int tx = threadIdx.x, ty = threadIdx.y;  // (32, 8)

    const float* src = f + (size_t)b * C_ * N_;
    float*       dst = g_ft + (size_t)b * N_ * C_;

#pragma unroll
    for (int i = 0; i < 32; i += 8)
        tile[ty + i][tx] = src[(size_t)(c0 + ty + i) * N_ + (n0 + tx)];
    __syncthreads();
#pragma unroll
    for (int i = 0; i < 32; i += 8)
        dst[(size_t)(n0 + ty + i) * C_ + (c0 + tx)] = tile[tx][ty + i];
}

// ---------------------------------------------------------------------------
// Kernel 2: ball query, smem-tiled to break the L2-latency chain.
// Block = 8 warps = 8 consecutive queries (all same batch b).
// Loop: cooperatively load 1024 points into smem (coalesced), then each
// not-yet-done warp scans them with 4 independent ballots per group.
// Early exit when all 8 warps have found 32 neighbors.
// ---------------------------------------------------------------------------
__global__ void ballquery_kernel(const float* __restrict__ xyz,
                                 const float* __restrict__ new_xyz) {
    __shared__ float spts[TILE_PTS * 3];   // interleaved x,y,z (stride-3 reads: conflict-free)
    __shared__ int   sidx[8][NS_];
    __shared__ int   s_done;

    const int w    = threadIdx.x >> 5;
    const int lane = threadIdx.x & 31;
    const int q    = blockIdx.x * 8 + w;   // global query id; b = q >> 10
    const int b    = q >> 10;

    const float* xb = xyz + (size_t)b * N_ * 3;
    const float* qp = new_xyz + (size_t)q * 3;
    const float qx = qp[0], qy = qp[1], qz = qp[2];

    if (threadIdx.x == 0) s_done = 0;

    int  total   = 0;
    bool done    = false;
    bool counted = false;
    const unsigned lanemask_lt = (1u << lane) - 1u;

    for (int t0 = 0; t0 < N_; t0 += TILE_PTS) {
        // Cooperative, fully coalesced load of 1024 points (3072 floats).
        const float* src = xb + (size_t)t0 * 3;
#pragma unroll
        for (int j = 0; j < 12; j++)
            spts[j * 256 + threadIdx.x] = src[j * 256 + threadIdx.x];
        __syncthreads();

        if (!done) {
            for (int c0 = 0; c0 < TILE_PTS / 32; c0 += 4) {
                unsigned msk[4];
#pragma unroll
                for (int j = 0; j < 4; j++) {
                    const int nl = (c0 + j) * 32 + lane;
                    const float dx = spts[3 * nl + 0] - qx;
                    const float dy = spts[3 * nl + 1] - qy;
                    const float dz = spts[3 * nl + 2] - qz;
                    const bool hit = dx * dx + dy * dy + dz * dz < R2_;
                    msk[j] = __ballot_sync(0xffffffffu, hit);
                }
#pragma unroll
                for (int j = 0; j < 4; j++) {
                    if (msk[j]) {
                        const int pos = total + __popc(msk[j] & lanemask_lt);
                        if (((msk[j] >> lane) & 1u) && pos < NS_)
                            sidx[w][pos] = t0 + (c0 + j) * 32 + lane;
                        total += __popc(msk[j]);
                    }
                }
                if (total >= NS_) { done = true; break; }
            }
            if (done && !counted) {
                counted = true;
                if (lane == 0) atomicAdd(&s_done, 1);
            }
        }
        __syncthreads();
        if (s_done == 8) break;
    }

    __syncwarp();
    int v;
    if (total == 0) {
        v = N_ - 1;  // reference yields idx=N+1 everywhere -> clamped gather
    } else {
        const int first = sidx[w][0];
        v = (lane < total) ? sidx[w][lane] : first;
    }
    g_idx[(size_t)q * NS_ + lane] = v;
}

// ---------------------------------------------------------------------------
// Kernel 3: grouping. One block per (b, m). Gather 64 contiguous channels per
// index from the transposed features (256B coalesced per sample), plus the
// xyz diff; stage in a 67x33 smem tile; write output fully coalesced.
// ---------------------------------------------------------------------------
__global__ void group_kernel(const float* __restrict__ xyz,
                             const float* __restrict__ new_xyz,
                             float* __restrict__ out) {
    __shared__ int   sidx[NS_];
    __shared__ float tile[COUT_][33];

    const int bm = blockIdx.x;
    const int b  = bm >> 10;
    const int m  = bm & (M_ - 1);
    const int t  = threadIdx.x;          // 256 threads
    const int w  = t >> 5;
    const int lane = t & 31;

    if (t < NS_) sidx[t] = g_idx[(size_t)bm * NS_ + t];
    __syncthreads();

    const float* ftb = g_ft + (size_t)b * N_ * C_;
    const float* qp  = new_xyz + ((size_t)b * M_ + m) * 3;

#pragma unroll
    for (int k = 0; k < 4; k++) {
        const int s = w + k * 8;         // 8 warps cover 32 samples
        const int n = sidx[s];
        const float* col = ftb + (size_t)n * C_;
        tile[3 + lane][s]      = col[lane];
        tile[3 + 32 + lane][s] = col[lane + 32];
        if (lane < 3)
            tile[lane][s] = xyz[((size_t)b * N_ + n) * 3 + lane] - qp[lane];
    }
    __syncthreads();

    float* ob = out + ((size_t)b * COUT_ * M_ + m) * NS_;
    for (int e = t; e < COUT_ * NS_; e += 256) {
        const int c = e >> 5;
        const int s = e & 31;
        ob[(size_t)c * M_ * NS_ + s] = tile[c][s];
    }
}

// ---------------------------------------------------------------------------
extern "C" void kernel_launch(void* const* d_in, const int* in_sizes, int n_in,
                              void* d_out, int out_size) {
    const float* xyz = nullptr;
    const float* new_xyz = nullptr;
    const float* feats = nullptr;
    for (int i = 0; i < n_in; i++) {
        if (in_sizes[i] == B_ * N_ * 3)      xyz     = (const float*)d_in[i];
        else if (in_sizes[i] == B_ * M_ * 3) new_xyz = (const float*)d_in[i];
        else if (in_sizes[i] == B_ * C_ * N_) feats  = (const float*)d_in[i];
    }
    float* out = (float*)d_out;

    ballquery_kernel<<<(B_ * M_) / 8, 256>>>(xyz, new_xyz);

    dim3 tgrid(N_ / 32, C_ / 32, B_);
    transpose_kernel<<<tgrid, dim3(32, 8)>>>(feats);

    group_kernel<<<B_ * M_, 256>>>(xyz, new_xyz, out);
}